// round 1
// baseline (speedup 1.0000x reference)
#include <cuda_runtime.h>
#include <math_constants.h>

#define NN 100000
#define NE 1000000
#define DD 64

// ---- static scratch (no allocation allowed) ----
__device__ __align__(16) float d_h[NN * DD];   // projected features per layer
__device__ __align__(16) float d_x[NN * DD];   // layer ping buffer
__device__ float d_asrc[NN];
__device__ float d_adst[NN];
__device__ int   d_rowstart[NN + 1];
__device__ int   d_cursor[NN];                 // counts, then scatter cursor
__device__ int   d_colsrc[NE];                 // CSR: src node per (dst-sorted) edge
__device__ int   d_bsums[128];

// ================= CSR build (runs once per call; dst fixed across layers) =================

__global__ void zero_counts_k() {
    int i = blockIdx.x * blockDim.x + threadIdx.x;
    if (i < NN) d_cursor[i] = 0;
}

__global__ void hist_k(const int* __restrict__ dst) {
    int e = blockIdx.x * blockDim.x + threadIdx.x;
    if (e < NE) atomicAdd(&d_cursor[dst[e]], 1);
}

__global__ void scan1_k() {
    __shared__ int sh[1024];
    int g = blockIdx.x * 1024 + threadIdx.x;
    int v = (g < NN) ? d_cursor[g] : 0;
    sh[threadIdx.x] = v;
    __syncthreads();
    for (int off = 1; off < 1024; off <<= 1) {
        int t = (threadIdx.x >= off) ? sh[threadIdx.x - off] : 0;
        __syncthreads();
        sh[threadIdx.x] += t;
        __syncthreads();
    }
    if (g < NN) d_rowstart[g] = sh[threadIdx.x] - v;   // exclusive within block
    if (threadIdx.x == 1023) d_bsums[blockIdx.x] = sh[1023];
}

__global__ void scan2_k(int nb) {
    __shared__ int sh[128];
    int t = threadIdx.x;
    int v = (t < nb) ? d_bsums[t] : 0;
    sh[t] = v;
    __syncthreads();
    for (int off = 1; off < 128; off <<= 1) {
        int u = (t >= off) ? sh[t - off] : 0;
        __syncthreads();
        sh[t] += u;
        __syncthreads();
    }
    if (t < nb) d_bsums[t] = sh[t] - v;   // exclusive block offsets
}

__global__ void scan3_k() {
    int g = blockIdx.x * 1024 + threadIdx.x;
    if (g < NN) {
        int r = d_rowstart[g] + d_bsums[blockIdx.x];
        d_rowstart[g] = r;
        d_cursor[g]   = r;   // scatter cursor starts at row start
    }
    if (g == 0) d_rowstart[NN] = NE;
}

__global__ void scatter_k(const int* __restrict__ src, const int* __restrict__ dst) {
    int e = blockIdx.x * blockDim.x + threadIdx.x;
    if (e < NE) {
        int p = atomicAdd(&d_cursor[dst[e]], 1);
        d_colsrc[p] = src[e];
    }
}

// ================= GEMM h = x @ W, fused attention logits a_src/a_dst =================
// Block: 64 rows x 64 cols, 256 threads, 4x4 outputs per thread.

__global__ __launch_bounds__(256) void gemm_attn_k(
        const float* __restrict__ x_ext, int use_internal,
        const float* __restrict__ W,
        const float* __restrict__ att_s, const float* __restrict__ att_d)
{
    const float* __restrict__ x = use_internal ? d_x : x_ext;
    __shared__ __align__(16) float ws[64 * 64];
    __shared__ __align__(16) float xs[64 * 68];   // pad 68 -> conflict-free k reads
    int tid  = threadIdx.x;
    int row0 = blockIdx.x * 64;

    for (int i = tid; i < 1024; i += 256)
        ((float4*)ws)[i] = ((const float4*)W)[i];
    for (int i = tid; i < 1024; i += 256) {
        int r = i >> 4, c4 = i & 15;
        float4 v = make_float4(0.f, 0.f, 0.f, 0.f);
        int gr = row0 + r;
        if (gr < NN) v = ((const float4*)x)[gr * 16 + c4];
        *(float4*)&xs[r * 68 + c4 * 4] = v;
    }
    __syncthreads();

    int tc = (tid & 15) * 4;
    int tr = (tid >> 4) * 4;
    float acc[4][4];
#pragma unroll
    for (int i = 0; i < 4; i++)
#pragma unroll
        for (int j = 0; j < 4; j++) acc[i][j] = 0.f;

#pragma unroll 16
    for (int k = 0; k < 64; k++) {
        float4 w4 = *(const float4*)&ws[k * 64 + tc];
#pragma unroll
        for (int i = 0; i < 4; i++) {
            float xv = xs[(tr + i) * 68 + k];
            acc[i][0] += xv * w4.x;
            acc[i][1] += xv * w4.y;
            acc[i][2] += xv * w4.z;
            acc[i][3] += xv * w4.w;
        }
    }

    float4 as4 = *(const float4*)&att_s[tc];
    float4 ad4 = *(const float4*)&att_d[tc];
#pragma unroll
    for (int i = 0; i < 4; i++) {
        int gr = row0 + tr + i;
        float ps = acc[i][0]*as4.x + acc[i][1]*as4.y + acc[i][2]*as4.z + acc[i][3]*as4.w;
        float pd = acc[i][0]*ad4.x + acc[i][1]*ad4.y + acc[i][2]*ad4.z + acc[i][3]*ad4.w;
#pragma unroll
        for (int off = 8; off; off >>= 1) {
            ps += __shfl_xor_sync(0xffffffffu, ps, off, 16);
            pd += __shfl_xor_sync(0xffffffffu, pd, off, 16);
        }
        if (gr < NN) {
            *(float4*)&d_h[gr * 64 + tc] =
                make_float4(acc[i][0], acc[i][1], acc[i][2], acc[i][3]);
            if ((tid & 15) == 0) { d_asrc[gr] = ps; d_adst[gr] = pd; }
        }
    }
}

// ================= Per-node segment softmax + weighted gather (warp per node) =================

__global__ __launch_bounds__(256) void aggregate_k(
        const float* __restrict__ bias, float* __restrict__ out_ext, int to_internal)
{
    float* __restrict__ out = to_internal ? d_x : out_ext;
    int wid  = (blockIdx.x * blockDim.x + threadIdx.x) >> 5;
    int lane = threadIdx.x & 31;
    if (wid >= NN) return;

    int beg = d_rowstart[wid];
    int end = d_rowstart[wid + 1];
    float b0 = bias[lane], b1 = bias[lane + 32];
    if (end == beg) {                       // isolated node: out = 0 + bias
        out[wid * 64 + lane]      = b0;
        out[wid * 64 + 32 + lane] = b1;
        return;
    }
    float adv = d_adst[wid];

    // pass 1: max
    float mx = -CUDART_INF_F;
    for (int j = beg + lane; j < end; j += 32) {
        float e = d_asrc[d_colsrc[j]] + adv;
        e = e > 0.f ? e : 0.2f * e;
        mx = fmaxf(mx, e);
    }
#pragma unroll
    for (int off = 16; off; off >>= 1)
        mx = fmaxf(mx, __shfl_xor_sync(0xffffffffu, mx, off));

    // pass 2: denominator
    float sm = 0.f;
    for (int j = beg + lane; j < end; j += 32) {
        float e = d_asrc[d_colsrc[j]] + adv;
        e = e > 0.f ? e : 0.2f * e;
        sm += __expf(e - mx);
    }
#pragma unroll
    for (int off = 16; off; off >>= 1)
        sm += __shfl_xor_sync(0xffffffffu, sm, off);
    float inv = 1.f / (sm + 1e-16f);

    // pass 3: weighted feature gather (coalesced 128B+128B per edge)
    float acc0 = 0.f, acc1 = 0.f;
    for (int j = beg; j < end; j++) {
        int s = d_colsrc[j];                 // broadcast across warp
        float e = d_asrc[s] + adv;
        e = e > 0.f ? e : 0.2f * e;
        float w = __expf(e - mx) * inv;
        acc0 += w * d_h[s * 64 + lane];
        acc1 += w * d_h[s * 64 + 32 + lane];
    }
    out[wid * 64 + lane]      = acc0 + b0;
    out[wid * 64 + 32 + lane] = acc1 + b1;
}

// ================= launch =================

extern "C" void kernel_launch(void* const* d_in, const int* in_sizes, int n_in,
                              void* d_out, int out_size)
{
    const float* g     = (const float*)d_in[0];
    const int*   ei    = (const int*)  d_in[1];
    const float* W     = (const float*)d_in[2];
    const float* att_s = (const float*)d_in[3];
    const float* att_d = (const float*)d_in[4];
    const float* bias  = (const float*)d_in[5];
    float* out = (float*)d_out;

    const int* src = ei;
    const int* dst = ei + NE;

    // CSR build (dst invariant across layers)
    zero_counts_k<<<(NN + 255) / 256, 256>>>();
    hist_k<<<(NE + 255) / 256, 256>>>(dst);
    int nb = (NN + 1023) / 1024;   // 98
    scan1_k<<<nb, 1024>>>();
    scan2_k<<<1, 128>>>(nb);
    scan3_k<<<nb, 1024>>>();
    scatter_k<<<(NE + 255) / 256, 256>>>(src, dst);

    const int gemm_blocks = (NN + 63) / 64;          // 1563
    const int agg_blocks  = (NN + 7) / 8;            // 12500 (8 warps/block)

    for (int L = 0; L < 4; L++) {
        gemm_attn_k<<<gemm_blocks, 256>>>(L == 0 ? g : nullptr, L == 0 ? 0 : 1,
                                          W, att_s, att_d);
        aggregate_k<<<agg_blocks, 256>>>(bias, L == 3 ? out : nullptr,
                                         L == 3 ? 0 : 1);
    }
}